// round 1
// baseline (speedup 1.0000x reference)
#include <cuda_runtime.h>
#include <math.h>

// Problem constants
#define B_  2
#define S_  2048
#define D_  1024
#define H_  16
#define HD_ 64
#define MS_ (B_ * S_)        // 4096 rows
#define NQKV_ (3 * D_)       // 3072

// Scratch (device globals: allocation inside kernel_launch is forbidden)
__device__ float g_qkv[(size_t)MS_ * NQKV_];  // [B,S,3*D] = Q|K|V packed
__device__ float g_att[(size_t)MS_ * D_];     // attention output [B,S,D]

// ---------------------------------------------------------------------------
// SGEMM: C[M,N] = A[M,K] @ B[K,N] + bias[N]
// 128x128 tile, BK=16, 256 threads, 8x8 per thread, float4 everywhere.
// Requires M%128==0, N%128==0, K%16==0 (true for all three shapes here).
// ---------------------------------------------------------------------------
__global__ void __launch_bounds__(256) sgemm_bias_kernel(
    const float* __restrict__ A, const float* __restrict__ Bm,
    const float* __restrict__ bias, float* __restrict__ C,
    int M, int N, int K)
{
    __shared__ float As[16][128];   // transposed A tile: As[k][m]
    __shared__ float Bs[16][128];   // Bs[k][n]

    const int tid  = threadIdx.x;
    const int tx   = tid & 15;      // 0..15 -> output col group
    const int ty   = tid >> 4;      // 0..15 -> output row group
    const int brow = blockIdx.y * 128;
    const int bcol = blockIdx.x * 128;

    // load mapping
    const int arow = tid >> 2;          // 0..63
    const int acol = (tid & 3) << 2;    // 0,4,8,12
    const int brw  = tid >> 5;          // 0..7
    const int bcl  = (tid & 31) << 2;   // 0..124

    float acc[8][8];
    #pragma unroll
    for (int i = 0; i < 8; i++)
        #pragma unroll
        for (int j = 0; j < 8; j++) acc[i][j] = 0.0f;

    for (int k0 = 0; k0 < K; k0 += 16) {
        float4 a0 = *(const float4*)(A + (size_t)(brow + arow)      * K + k0 + acol);
        float4 a1 = *(const float4*)(A + (size_t)(brow + arow + 64) * K + k0 + acol);
        As[acol + 0][arow] = a0.x;  As[acol + 1][arow] = a0.y;
        As[acol + 2][arow] = a0.z;  As[acol + 3][arow] = a0.w;
        As[acol + 0][arow + 64] = a1.x;  As[acol + 1][arow + 64] = a1.y;
        As[acol + 2][arow + 64] = a1.z;  As[acol + 3][arow + 64] = a1.w;

        float4 b0 = *(const float4*)(Bm + (size_t)(k0 + brw)     * N + bcol + bcl);
        float4 b1 = *(const float4*)(Bm + (size_t)(k0 + brw + 8) * N + bcol + bcl);
        *(float4*)&Bs[brw][bcl]     = b0;
        *(float4*)&Bs[brw + 8][bcl] = b1;

        __syncthreads();

        #pragma unroll
        for (int k = 0; k < 16; k++) {
            float4 a04 = *(float4*)&As[k][ty * 8];
            float4 a14 = *(float4*)&As[k][ty * 8 + 4];
            float4 b04 = *(float4*)&Bs[k][tx * 8];
            float4 b14 = *(float4*)&Bs[k][tx * 8 + 4];
            float av[8] = {a04.x, a04.y, a04.z, a04.w, a14.x, a14.y, a14.z, a14.w};
            float bv[8] = {b04.x, b04.y, b04.z, b04.w, b14.x, b14.y, b14.z, b14.w};
            #pragma unroll
            for (int i = 0; i < 8; i++)
                #pragma unroll
                for (int j = 0; j < 8; j++)
                    acc[i][j] = fmaf(av[i], bv[j], acc[i][j]);
        }
        __syncthreads();
    }

    float bv[8];
    #pragma unroll
    for (int j = 0; j < 8; j++) bv[j] = bias[bcol + tx * 8 + j];

    #pragma unroll
    for (int i = 0; i < 8; i++) {
        float* Crow = C + (size_t)(brow + ty * 8 + i) * N + bcol + tx * 8;
        float4 o0 = make_float4(acc[i][0] + bv[0], acc[i][1] + bv[1],
                                acc[i][2] + bv[2], acc[i][3] + bv[3]);
        float4 o1 = make_float4(acc[i][4] + bv[4], acc[i][5] + bv[5],
                                acc[i][6] + bv[6], acc[i][7] + bv[7]);
        *(float4*)(Crow)     = o0;
        *(float4*)(Crow + 4) = o1;
    }
}

// ---------------------------------------------------------------------------
// Flash attention, fp32. One CTA per (q-tile of 64 rows, head, batch).
// 256 threads as 16x16; each thread owns a 4x4 logit/output patch.
// Streaming softmax over K-tiles of 64; causal tiles (kt>qt) skipped.
// Dynamic smem: Qs[64][65] | KVs[64][65] | Ps[64][65]  = 49,920 B
// ---------------------------------------------------------------------------
#define FA_PAD 65
#define FA_SMEM (3 * 64 * FA_PAD * 4)

__global__ void __launch_bounds__(256) flash_attn_kernel()
{
    extern __shared__ float sm[];
    float* Qs  = sm;                     // [64][65]
    float* KVs = sm + 64 * FA_PAD;       // [64][65]  (K tile then V tile)
    float* Ps  = sm + 2 * 64 * FA_PAD;   // [64][65]

    const int tid = threadIdx.x;
    const int tx  = tid & 15;
    const int ty  = tid >> 4;
    const int qt  = blockIdx.x;          // 0..31
    const int h   = blockIdx.y;          // 0..15
    const int b   = blockIdx.z;          // 0..1
    const float scale = 0.125f;          // 1/sqrt(64)

    const size_t base = (size_t)b * S_ * NQKV_;
    const int hoff = h * HD_;

    // Load Q tile (coalesced: consecutive tid -> consecutive d)
    for (int i = tid; i < 64 * 64; i += 256) {
        int r = i >> 6, d = i & 63;
        Qs[r * FA_PAD + d] =
            g_qkv[base + (size_t)(qt * 64 + r) * NQKV_ + hoff + d];
    }

    float m[4], l[4], O[4][4];
    #pragma unroll
    for (int r = 0; r < 4; r++) {
        m[r] = -INFINITY; l[r] = 0.0f;
        #pragma unroll
        for (int c = 0; c < 4; c++) O[r][c] = 0.0f;
    }

    for (int kt = 0; kt <= qt; kt++) {
        __syncthreads();   // prev iter done reading KVs(V)/Ps; Q load visible
        // Load K tile: KVs[key][d]
        for (int i = tid; i < 64 * 64; i += 256) {
            int r = i >> 6, d = i & 63;
            KVs[r * FA_PAD + d] =
                g_qkv[base + (size_t)(kt * 64 + r) * NQKV_ + D_ + hoff + d];
        }
        __syncthreads();

        // S = Q @ K^T  (4x4 per thread)
        float s[4][4];
        #pragma unroll
        for (int r = 0; r < 4; r++)
            #pragma unroll
            for (int c = 0; c < 4; c++) s[r][c] = 0.0f;

        #pragma unroll 8
        for (int d = 0; d < 64; d++) {
            float qv[4], kv[4];
            #pragma unroll
            for (int r = 0; r < 4; r++) qv[r] = Qs[(4 * ty + r) * FA_PAD + d];
            #pragma unroll
            for (int c = 0; c < 4; c++) kv[c] = KVs[(4 * tx + c) * FA_PAD + d];
            #pragma unroll
            for (int r = 0; r < 4; r++)
                #pragma unroll
                for (int c = 0; c < 4; c++)
                    s[r][c] = fmaf(qv[r], kv[c], s[r][c]);
        }

        // Causal mask + scale (mask -> -inf, matching where(mask,-inf,.)*scale)
        #pragma unroll
        for (int r = 0; r < 4; r++) {
            int qi = qt * 64 + 4 * ty + r;
            #pragma unroll
            for (int c = 0; c < 4; c++) {
                int kj = kt * 64 + 4 * tx + c;
                s[r][c] = (kj <= qi) ? s[r][c] * scale : -INFINITY;
            }
        }

        // Streaming softmax update (row groups of 16 lanes, xor<16 stays in group)
        #pragma unroll
        for (int r = 0; r < 4; r++) {
            float rm = fmaxf(fmaxf(s[r][0], s[r][1]), fmaxf(s[r][2], s[r][3]));
            #pragma unroll
            for (int o = 8; o >= 1; o >>= 1)
                rm = fmaxf(rm, __shfl_xor_sync(0xffffffffu, rm, o));
            float mn   = fmaxf(m[r], rm);
            float corr = __expf(m[r] - mn);
            float rs = 0.0f;
            #pragma unroll
            for (int c = 0; c < 4; c++) {
                float p = __expf(s[r][c] - mn);
                s[r][c] = p;
                rs += p;
            }
            #pragma unroll
            for (int o = 8; o >= 1; o >>= 1)
                rs += __shfl_xor_sync(0xffffffffu, rs, o);
            l[r] = l[r] * corr + rs;
            m[r] = mn;
            #pragma unroll
            for (int c = 0; c < 4; c++) O[r][c] *= corr;
        }

        // Write P to smem
        #pragma unroll
        for (int r = 0; r < 4; r++)
            #pragma unroll
            for (int c = 0; c < 4; c++)
                Ps[(4 * ty + r) * FA_PAD + (4 * tx + c)] = s[r][c];

        __syncthreads();   // everyone done with KVs(K); Ps fully written

        // Load V tile into KVs: KVs[key][d]
        for (int i = tid; i < 64 * 64; i += 256) {
            int r = i >> 6, d = i & 63;
            KVs[r * FA_PAD + d] =
                g_qkv[base + (size_t)(kt * 64 + r) * NQKV_ + 2 * D_ + hoff + d];
        }
        __syncthreads();

        // O += P @ V
        #pragma unroll 8
        for (int j = 0; j < 64; j++) {
            float pv[4], vv[4];
            #pragma unroll
            for (int r = 0; r < 4; r++) pv[r] = Ps[(4 * ty + r) * FA_PAD + j];
            #pragma unroll
            for (int c = 0; c < 4; c++) vv[c] = KVs[j * FA_PAD + 4 * tx + c];
            #pragma unroll
            for (int r = 0; r < 4; r++)
                #pragma unroll
                for (int c = 0; c < 4; c++)
                    O[r][c] = fmaf(pv[r], vv[c], O[r][c]);
        }
    }

    // Normalize and write out: att[b, q, h*64 + d]
    #pragma unroll
    for (int r = 0; r < 4; r++) {
        float inv = 1.0f / l[r];
        size_t row = (size_t)b * S_ + qt * 64 + 4 * ty + r;
        float4 o = make_float4(O[r][0] * inv, O[r][1] * inv,
                               O[r][2] * inv, O[r][3] * inv);
        *(float4*)&g_att[row * D_ + hoff + 4 * tx] = o;
    }
}

// ---------------------------------------------------------------------------
// kernel_launch: QKV GEMM -> flash attention -> output GEMM
// ---------------------------------------------------------------------------
extern "C" void kernel_launch(void* const* d_in, const int* in_sizes, int n_in,
                              void* d_out, int out_size)
{
    const float* x     = (const float*)d_in[0];   // [B,S,D]
    const float* qkv_w = (const float*)d_in[1];   // [D,3D]
    const float* qkv_b = (const float*)d_in[2];   // [3D]
    const float* out_w = (const float*)d_in[3];   // [D,D]
    const float* out_b = (const float*)d_in[4];   // [D]
    float* out = (float*)d_out;                   // [B,S,D]

    float *qkv_buf, *att_buf;
    cudaGetSymbolAddress((void**)&qkv_buf, g_qkv);
    cudaGetSymbolAddress((void**)&att_buf, g_att);

    // 1) QKV projection: [4096,1024] @ [1024,3072] + b
    {
        dim3 grid(NQKV_ / 128, MS_ / 128);
        sgemm_bias_kernel<<<grid, 256>>>(x, qkv_w, qkv_b, qkv_buf,
                                         MS_, NQKV_, D_);
    }

    // 2) Flash attention
    {
        cudaFuncSetAttribute(flash_attn_kernel,
                             cudaFuncAttributeMaxDynamicSharedMemorySize,
                             FA_SMEM);
        dim3 grid(S_ / 64, H_, B_);
        flash_attn_kernel<<<grid, 256, FA_SMEM>>>();
    }

    // 3) Output projection: [4096,1024] @ [1024,1024] + b
    {
        dim3 grid(D_ / 128, MS_ / 128);
        sgemm_bias_kernel<<<grid, 256>>>(att_buf, out_w, out_b, out,
                                         MS_, D_, D_);
    }
}

// round 6
// speedup vs baseline: 1.4226x; 1.4226x over previous
#include <cuda_runtime.h>
#include <cuda_bf16.h>
#include <math.h>
#include <stdint.h>

// Problem constants
#define B_  2
#define S_  2048
#define D_  1024
#define H_  16
#define HD_ 64
#define MS_ (B_ * S_)        // 4096 rows
#define NQKV_ (3 * D_)       // 3072

// ---------------------------------------------------------------------------
// Device-global scratch (no allocations allowed in kernel_launch)
// ---------------------------------------------------------------------------
__device__ float g_qkv[(size_t)MS_ * NQKV_];   // QKV projection output (fp32)
__device__ float g_att[(size_t)MS_ * D_];      // attention output (fp32)

// bf16 splits: A operands (row-major [M,K]) and transposed weights ([N,K])
__device__ __nv_bfloat16 g_xh[(size_t)MS_ * D_],  g_xl[(size_t)MS_ * D_];
__device__ __nv_bfloat16 g_wh[(size_t)NQKV_ * D_], g_wl[(size_t)NQKV_ * D_]; // qkv_w^T
__device__ __nv_bfloat16 g_oh[(size_t)D_ * D_],   g_ol[(size_t)D_ * D_];     // out_w^T
__device__ __nv_bfloat16 g_ah[(size_t)MS_ * D_],  g_al[(size_t)MS_ * D_];    // att split

// ---------------------------------------------------------------------------
// Base-ISA async copy (sm_80+) — NOT tcgen05/TMA ('a'-suffix features are
// unavailable: harness compiles PTX for compute_103 base target).
// ---------------------------------------------------------------------------
#define CP_ASYNC16(dst_u32, src_ptr) \
    asm volatile("cp.async.cg.shared.global [%0], [%1], 16;" \
                 :: "r"(dst_u32), "l"(src_ptr) : "memory")
#define CP_COMMIT() asm volatile("cp.async.commit_group;" ::: "memory")
#define CP_WAIT(n)  asm volatile("cp.async.wait_group %0;" :: "n"(n) : "memory")

__device__ __forceinline__ uint32_t smem_u32(const void* p) {
    uint32_t a;
    asm("{ .reg .u64 t; cvta.to.shared.u64 t, %1; cvt.u32.u64 %0, t; }"
        : "=r"(a) : "l"(p));
    return a;
}

// bf16 HMMA, fp32 accumulate (base ISA, sm_80+)
__device__ __forceinline__ void mma_bf16(float* c, const uint32_t* a,
                                         const uint32_t* b) {
    asm volatile(
        "mma.sync.aligned.m16n8k16.row.col.f32.bf16.bf16.f32 "
        "{%0,%1,%2,%3}, {%4,%5,%6,%7}, {%8,%9}, {%0,%1,%2,%3};"
        : "+f"(c[0]), "+f"(c[1]), "+f"(c[2]), "+f"(c[3])
        : "r"(a[0]), "r"(a[1]), "r"(a[2]), "r"(a[3]), "r"(b[0]), "r"(b[1]));
}

// ---------------------------------------------------------------------------
// Split kernels: fp32 -> bf16 hi + bf16 lo  (lo = bf16(x - float(hi)))
// ---------------------------------------------------------------------------
__global__ void __launch_bounds__(256) split_kernel(
    const float4* __restrict__ src, __nv_bfloat162* __restrict__ hi,
    __nv_bfloat162* __restrict__ lo, int n4)
{
    int i = blockIdx.x * 256 + threadIdx.x;
    if (i >= n4) return;
    float4 v = src[i];
    __nv_bfloat16 h0 = __float2bfloat16(v.x), h1 = __float2bfloat16(v.y);
    __nv_bfloat16 h2 = __float2bfloat16(v.z), h3 = __float2bfloat16(v.w);
    __nv_bfloat16 l0 = __float2bfloat16(v.x - __bfloat162float(h0));
    __nv_bfloat16 l1 = __float2bfloat16(v.y - __bfloat162float(h1));
    __nv_bfloat16 l2 = __float2bfloat16(v.z - __bfloat162float(h2));
    __nv_bfloat16 l3 = __float2bfloat16(v.w - __bfloat162float(h3));
    __nv_bfloat162 a; a.x = h0; a.y = h1;
    __nv_bfloat162 b; b.x = h2; b.y = h3;
    __nv_bfloat162 c; c.x = l0; c.y = l1;
    __nv_bfloat162 d; d.x = l2; d.y = l3;
    hi[2 * i] = a;  hi[2 * i + 1] = b;
    lo[2 * i] = c;  lo[2 * i + 1] = d;
}

// Split + transpose: src [R,C] fp32 row-major -> hi/lo [C,R] bf16 row-major
__global__ void __launch_bounds__(256) split_transpose_kernel(
    const float* __restrict__ src, __nv_bfloat16* __restrict__ hi,
    __nv_bfloat16* __restrict__ lo, int R, int C)
{
    __shared__ float t[32][33];
    int c0 = blockIdx.x * 32, r0 = blockIdx.y * 32;
    int tx = threadIdx.x, ty = threadIdx.y;
    #pragma unroll
    for (int i = 0; i < 4; i++) {
        int r = r0 + ty + i * 8;
        t[ty + i * 8][tx] = src[(size_t)r * C + c0 + tx];
    }
    __syncthreads();
    #pragma unroll
    for (int i = 0; i < 4; i++) {
        int n = c0 + ty + i * 8;
        float v = t[tx][ty + i * 8];
        __nv_bfloat16 h = __float2bfloat16(v);
        hi[(size_t)n * R + r0 + tx] = h;
        lo[(size_t)n * R + r0 + tx] = __float2bfloat16(v - __bfloat162float(h));
    }
}

// ---------------------------------------------------------------------------
// HMMA bf16-split GEMM: C[M,N] = A[M,K] @ Bt[N,K]^T + bias
//   C = Ah*Bh + Ah*Bl + Al*Bh   (fp32 accumulate)
// CTA tile 128x128x32; 8 warps as 4(m) x 2(n): warp tile 32m x 64n.
// smem per tile: 128 rows x 20 u32 (16 data + 4 pad -> conflict-free quads).
// cp.async double-buffered.
// ---------------------------------------------------------------------------
#define BM 128
#define BN 128
#define BK 32
#define ROW_U32 20
#define TILE_U32 (128 * ROW_U32)                 // 2560
#define STAGE_U32 (4 * TILE_U32)                 // AH|AL|BH|BL = 10240
#define GEMM_SMEM (2 * STAGE_U32 * 4)            // 81920 bytes

__global__ void __launch_bounds__(256)
gemm_mma_kernel(const __nv_bfloat16* __restrict__ Ah,
                const __nv_bfloat16* __restrict__ Al,
                const __nv_bfloat16* __restrict__ Bth,
                const __nv_bfloat16* __restrict__ Btl,
                const float* __restrict__ bias, float* __restrict__ C,
                int M, int N, int K)
{
    extern __shared__ uint32_t smem[];
    const uint32_t sb = smem_u32(smem);

    const int tid  = threadIdx.x;
    const int wid  = tid >> 5;
    const int lane = tid & 31;
    const int gid  = lane >> 2;     // 0..7
    const int tig  = lane & 3;      // 0..3
    const int wm   = (wid & 3) * 32;   // warp m base in tile
    const int wn   = (wid >> 2) * 64;  // warp n base in tile

    const int brow = blockIdx.y * BM;
    const int bcol = blockIdx.x * BN;

    // prefetch mapping: each thread loads 2 rows per tile (prow, prow+64)
    const int prow = tid >> 2;      // 0..63
    const int pc4  = tid & 3;       // 16B chunk within 64B row

    const __nv_bfloat16* srcs[4];
    srcs[0] = Ah  + (size_t)(brow + prow) * K + pc4 * 8;
    srcs[1] = Al  + (size_t)(brow + prow) * K + pc4 * 8;
    srcs[2] = Bth + (size_t)(bcol + prow) * K + pc4 * 8;
    srcs[3] = Btl + (size_t)(bcol + prow) * K + pc4 * 8;

    const uint32_t dst_base = sb + 4u * ((uint32_t)prow * ROW_U32 + pc4 * 4);

    const int NKB = K / BK;

    // Prologue: stage 0 <- k-block 0
    #pragma unroll
    for (int t = 0; t < 4; t++) {
        uint32_t d = dst_base + 4u * (uint32_t)(t * TILE_U32);
        CP_ASYNC16(d, srcs[t]);
        CP_ASYNC16(d + 4u * 64u * ROW_U32, srcs[t] + (size_t)64 * K);
    }
    CP_COMMIT();

    float acc[2][8][4];
    #pragma unroll
    for (int mt = 0; mt < 2; mt++)
        #pragma unroll
        for (int nt = 0; nt < 8; nt++)
            #pragma unroll
            for (int e = 0; e < 4; e++) acc[mt][nt][e] = 0.0f;

    for (int kb = 0; kb < NKB; kb++) {
        if (kb + 1 < NKB) {
            const int k0 = (kb + 1) * BK;
            const uint32_t stg = 4u * (uint32_t)(((kb + 1) & 1) * STAGE_U32);
            #pragma unroll
            for (int t = 0; t < 4; t++) {
                uint32_t d = dst_base + stg + 4u * (uint32_t)(t * TILE_U32);
                CP_ASYNC16(d, srcs[t] + k0);
                CP_ASYNC16(d + 4u * 64u * ROW_U32, srcs[t] + k0 + (size_t)64 * K);
            }
            CP_COMMIT();
            CP_WAIT(1);
        } else {
            CP_WAIT(0);
        }
        __syncthreads();

        const uint32_t* st   = smem + (kb & 1) * STAGE_U32;
        const uint32_t* Ah_s = st;
        const uint32_t* Al_s = st + TILE_U32;
        const uint32_t* Bh_s = st + 2 * TILE_U32;
        const uint32_t* Bl_s = st + 3 * TILE_U32;

        #pragma unroll
        for (int ks = 0; ks < 2; ks++) {
            const int k0u = ks * 8;
            uint32_t ah[2][4], al[2][4];
            #pragma unroll
            for (int mt = 0; mt < 2; mt++) {
                const int r = wm + mt * 16 + gid;
                ah[mt][0] = Ah_s[r * ROW_U32 + k0u + tig];
                ah[mt][1] = Ah_s[(r + 8) * ROW_U32 + k0u + tig];
                ah[mt][2] = Ah_s[r * ROW_U32 + k0u + 4 + tig];
                ah[mt][3] = Ah_s[(r + 8) * ROW_U32 + k0u + 4 + tig];
                al[mt][0] = Al_s[r * ROW_U32 + k0u + tig];
                al[mt][1] = Al_s[(r + 8) * ROW_U32 + k0u + tig];
                al[mt][2] = Al_s[r * ROW_U32 + k0u + 4 + tig];
                al[mt][3] = Al_s[(r + 8) * ROW_U32 + k0u + 4 + tig];
            }
            #pragma unroll
            for (int nt = 0; nt < 8; nt++) {
                const int n = wn + nt * 8 + gid;
                uint32_t bh[2], bl[2];
                bh[0] = Bh_s[n * ROW_U32 + k0u + tig];
                bh[1] = Bh_s[n * ROW_U32 + k0u + 4 + tig];
                bl[0] = Bl_s[n * ROW_U32 + k0u + tig];
                bl[1] = Bl_s[n * ROW_U32 + k0u + 4 + tig];
                #pragma unroll
                for (int mt = 0; mt < 2; mt++) {
                    mma_bf16(acc[mt][nt], ah[mt], bh);
                    mma_bf16(acc[mt][nt], ah[mt], bl);
                    mma_bf16(acc[mt][nt], al[mt], bh);
                }
            }
        }
        __syncthreads();
    }

    // Epilogue: direct float2 stores + bias
    #pragma unroll
    for (int mt = 0; mt < 2; mt++) {
        const int gr = brow + wm + mt * 16 + gid;
        #pragma unroll
        for (int nt = 0; nt < 8; nt++) {
            const int gc = bcol + wn + nt * 8 + tig * 2;
            const float2 bb = *(const float2*)(bias + gc);
            float2 o0, o1;
            o0.x = acc[mt][nt][0] + bb.x;  o0.y = acc[mt][nt][1] + bb.y;
            o1.x = acc[mt][nt][2] + bb.x;  o1.y = acc[mt][nt][3] + bb.y;
            *(float2*)(C + (size_t)gr * N + gc)       = o0;
            *(float2*)(C + (size_t)(gr + 8) * N + gc) = o1;
        }
    }
}

// ---------------------------------------------------------------------------
// Flash attention, fp32 (known-passing R1 version — next round's target)
// ---------------------------------------------------------------------------
#define FA_PAD 65
#define FA_SMEM (3 * 64 * FA_PAD * 4)

__global__ void __launch_bounds__(256) flash_attn_kernel()
{
    extern __shared__ float sm[];
    float* Qs  = sm;
    float* KVs = sm + 64 * FA_PAD;
    float* Ps  = sm + 2 * 64 * FA_PAD;

    const int tid = threadIdx.x;
    const int tx  = tid & 15;
    const int ty  = tid >> 4;
    const int qt  = blockIdx.x;
    const int h   = blockIdx.y;
    const int b   = blockIdx.z;
    const float scale = 0.125f;

    const size_t base = (size_t)b * S_ * NQKV_;
    const int hoff = h * HD_;

    for (int i = tid; i < 64 * 64; i += 256) {
        int r = i >> 6, d = i & 63;
        Qs[r * FA_PAD + d] = g_qkv[base + (size_t)(qt * 64 + r) * NQKV_ + hoff + d];
    }

    float m[4], l[4], O[4][4];
    #pragma unroll
    for (int r = 0; r < 4; r++) {
        m[r] = -INFINITY; l[r] = 0.0f;
        #pragma unroll
        for (int c = 0; c < 4; c++) O[r][c] = 0.0f;
    }

    for (int kt = 0; kt <= qt; kt++) {
        __syncthreads();
        for (int i = tid; i < 64 * 64; i += 256) {
            int r = i >> 6, d = i & 63;
            KVs[r * FA_PAD + d] =
                g_qkv[base + (size_t)(kt * 64 + r) * NQKV_ + D_ + hoff + d];
        }
        __syncthreads();

        float s[4][4];
        #pragma unroll
        for (int r = 0; r < 4; r++)
            #pragma unroll
            for (int c = 0; c < 4; c++) s[r][c] = 0.0f;

        #pragma unroll 8
        for (int d = 0; d < 64; d++) {
            float qv[4], kv[4];
            #pragma unroll
            for (int r = 0; r < 4; r++) qv[r] = Qs[(4 * ty + r) * FA_PAD + d];
            #pragma unroll
            for (int c = 0; c < 4; c++) kv[c] = KVs[(4 * tx + c) * FA_PAD + d];
            #pragma unroll
            for (int r = 0; r < 4; r++)
                #pragma unroll
                for (int c = 0; c < 4; c++)
                    s[r][c] = fmaf(qv[r], kv[c], s[r][c]);
        }

        #pragma unroll
        for (int r = 0; r < 4; r++) {
            int qi = qt * 64 + 4 * ty + r;
            #pragma unroll
            for (int c = 0; c < 4; c++) {
                int kj = kt * 64 + 4 * tx + c;
                s[r][c] = (kj <= qi) ? s[r][c] * scale : -INFINITY;
            }
        }

        #pragma unroll
        for (int r = 0; r < 4; r++) {
            float rm = fmaxf(fmaxf(s[r][0], s[r][1]), fmaxf(s[r][2], s[r][3]));
            #pragma unroll
            for (int o = 8; o >= 1; o >>= 1)
                rm = fmaxf(rm, __shfl_xor_sync(0xffffffffu, rm, o));
            float mn   = fmaxf(m[r], rm);
            float corr = __expf(m[r] - mn);
            float rs = 0.0f;
            #pragma unroll
            for (int c = 0; c < 4; c++) {
                float p = __expf(s[r][c] - mn);
                s[r][c] = p;
                rs += p;
            }
            #pragma unroll
            for (int o = 8; o >= 1; o >>= 1)
                rs += __shfl_xor_sync(0xffffffffu, rs, o);
            l[r] = l[r] * corr + rs;
            m[r] = mn;
            #pragma unroll
            for (int c = 0; c < 4; c++) O[r][c] *= corr;
        }

        #pragma unroll
        for (int r = 0; r < 4; r++)
            #pragma unroll
            for (int c = 0; c < 4; c++)
                Ps[(4 * ty + r) * FA_PAD + (4 * tx + c)] = s[r][c];

        __syncthreads();

        for (int i = tid; i < 64 * 64; i += 256) {
            int r = i >> 6, d = i & 63;
            KVs[r * FA_PAD + d] =
                g_qkv[base + (size_t)(kt * 64 + r) * NQKV_ + 2 * D_ + hoff + d];
        }
        __syncthreads();

        #pragma unroll 8
        for (int j = 0; j < 64; j++) {
            float pv[4], vv[4];
            #pragma unroll
            for (int r = 0; r < 4; r++) pv[r] = Ps[(4 * ty + r) * FA_PAD + j];
            #pragma unroll
            for (int c = 0; c < 4; c++) vv[c] = KVs[j * FA_PAD + 4 * tx + c];
            #pragma unroll
            for (int r = 0; r < 4; r++)
                #pragma unroll
                for (int c = 0; c < 4; c++)
                    O[r][c] = fmaf(pv[r], vv[c], O[r][c]);
        }
    }

    #pragma unroll
    for (int r = 0; r < 4; r++) {
        float inv = 1.0f / l[r];
        size_t row = (size_t)b * S_ + qt * 64 + 4 * ty + r;
        float4 o = make_float4(O[r][0] * inv, O[r][1] * inv,
                               O[r][2] * inv, O[r][3] * inv);
        *(float4*)&g_att[row * D_ + hoff + 4 * tx] = o;
    }
}

// ---------------------------------------------------------------------------
// kernel_launch
// ---------------------------------------------------------------------------
extern "C" void kernel_launch(void* const* d_in, const int* in_sizes, int n_in,
                              void* d_out, int out_size)
{
    const float* x     = (const float*)d_in[0];
    const float* qkv_w = (const float*)d_in[1];
    const float* qkv_b = (const float*)d_in[2];
    const float* out_w = (const float*)d_in[3];
    const float* out_b = (const float*)d_in[4];
    float* out = (float*)d_out;

    float *qkv_buf, *att_buf;
    __nv_bfloat16 *xh, *xl, *wh, *wl, *oh, *ol, *ah, *al;
    cudaGetSymbolAddress((void**)&qkv_buf, g_qkv);
    cudaGetSymbolAddress((void**)&att_buf, g_att);
    cudaGetSymbolAddress((void**)&xh, g_xh);
    cudaGetSymbolAddress((void**)&xl, g_xl);
    cudaGetSymbolAddress((void**)&wh, g_wh);
    cudaGetSymbolAddress((void**)&wl, g_wl);
    cudaGetSymbolAddress((void**)&oh, g_oh);
    cudaGetSymbolAddress((void**)&ol, g_ol);
    cudaGetSymbolAddress((void**)&ah, g_ah);
    cudaGetSymbolAddress((void**)&al, g_al);

    cudaFuncSetAttribute(gemm_mma_kernel,
                         cudaFuncAttributeMaxDynamicSharedMemorySize, GEMM_SMEM);
    cudaFuncSetAttribute(flash_attn_kernel,
                         cudaFuncAttributeMaxDynamicSharedMemorySize, FA_SMEM);

    // Split inputs
    {
        int n4 = MS_ * D_ / 4;
        split_kernel<<<(n4 + 255) / 256, 256>>>(
            (const float4*)x, (__nv_bfloat162*)xh, (__nv_bfloat162*)xl, n4);
    }
    split_transpose_kernel<<<dim3(NQKV_ / 32, D_ / 32), dim3(32, 8)>>>(
        qkv_w, wh, wl, D_, NQKV_);
    split_transpose_kernel<<<dim3(D_ / 32, D_ / 32), dim3(32, 8)>>>(
        out_w, oh, ol, D_, D_);

    // 1) QKV projection (HMMA tensor cores)
    gemm_mma_kernel<<<dim3(NQKV_ / BN, MS_ / BM), 256, GEMM_SMEM>>>(
        xh, xl, wh, wl, qkv_b, qkv_buf, MS_, NQKV_, D_);

    // 2) Flash attention (fp32)
    flash_attn_kernel<<<dim3(S_ / 64, H_, B_), 256, FA_SMEM>>>();

    // 3) Split attention output, then output projection (HMMA)
    {
        int n4 = MS_ * D_ / 4;
        split_kernel<<<(n4 + 255) / 256, 256>>>(
            (const float4*)att_buf, (__nv_bfloat162*)ah, (__nv_bfloat162*)al, n4);
    }
    gemm_mma_kernel<<<dim3(D_ / BN, MS_ / BM), 256, GEMM_SMEM>>>(
        ah, al, oh, ol, out_b, out, MS_, D_, D_);
}

// round 11
// speedup vs baseline: 2.4823x; 1.7449x over previous
#include <cuda_runtime.h>
#include <cuda_bf16.h>
#include <math.h>
#include <stdint.h>

// Problem constants
#define B_  2
#define S_  2048
#define D_  1024
#define H_  16
#define HD_ 64
#define MS_ (B_ * S_)        // 4096 rows
#define NQKV_ (3 * D_)       // 3072

// ---------------------------------------------------------------------------
// Device-global scratch
// ---------------------------------------------------------------------------
__device__ float g_qkv[(size_t)MS_ * NQKV_];   // QKV projection output (fp32)
__device__ float g_att[(size_t)MS_ * D_];      // attention output (fp32)

__device__ __nv_bfloat16 g_xh[(size_t)MS_ * D_],  g_xl[(size_t)MS_ * D_];
__device__ __nv_bfloat16 g_wh[(size_t)NQKV_ * D_], g_wl[(size_t)NQKV_ * D_];
__device__ __nv_bfloat16 g_oh[(size_t)D_ * D_],   g_ol[(size_t)D_ * D_];
__device__ __nv_bfloat16 g_ah[(size_t)MS_ * D_],  g_al[(size_t)MS_ * D_];

// flash operand arrays (bf16 split, permuted u32-pair layout)
// q/k: [b,h,s,d]  (32 u32 per row of 64 d)   v: [b,h,d,s] (1024 u32 per d-row)
#define FQK_ELEMS ((size_t)B_ * H_ * S_ * HD_)
__device__ __nv_bfloat16 g_fqh[FQK_ELEMS], g_fql[FQK_ELEMS];
__device__ __nv_bfloat16 g_fkh[FQK_ELEMS], g_fkl[FQK_ELEMS];
__device__ __nv_bfloat16 g_fvh[FQK_ELEMS], g_fvl[FQK_ELEMS];

// ---------------------------------------------------------------------------
// Base-ISA helpers (no tcgen05/TMA: harness compiles for compute_103 base)
// ---------------------------------------------------------------------------
#define CP_ASYNC16(dst_u32, src_ptr) \
    asm volatile("cp.async.cg.shared.global [%0], [%1], 16;" \
                 :: "r"(dst_u32), "l"(src_ptr) : "memory")
#define CP_COMMIT() asm volatile("cp.async.commit_group;" ::: "memory")
#define CP_WAIT(n)  asm volatile("cp.async.wait_group %0;" :: "n"(n) : "memory")

__device__ __forceinline__ uint32_t smem_u32(const void* p) {
    uint32_t a;
    asm("{ .reg .u64 t; cvta.to.shared.u64 t, %1; cvt.u32.u64 %0, t; }"
        : "=r"(a) : "l"(p));
    return a;
}

// bf16 HMMA m16n8k16, fp32 accumulate (validated in R6)
__device__ __forceinline__ void mma_bf16(float* c, const uint32_t* a,
                                         const uint32_t* b) {
    asm volatile(
        "mma.sync.aligned.m16n8k16.row.col.f32.bf16.bf16.f32 "
        "{%0,%1,%2,%3}, {%4,%5,%6,%7}, {%8,%9}, {%0,%1,%2,%3};"
        : "+f"(c[0]), "+f"(c[1]), "+f"(c[2]), "+f"(c[3])
        : "r"(a[0]), "r"(a[1]), "r"(a[2]), "r"(a[3]), "r"(b[0]), "r"(b[1]));
}

// split a float pair into packed bf16x2 hi and lo (lo-elem in low half)
__device__ __forceinline__ void psplit(float vlo, float vhi,
                                       uint32_t& hp, uint32_t& lp) {
    asm("cvt.rn.bf16x2.f32 %0, %1, %2;" : "=r"(hp) : "f"(vhi), "f"(vlo));
    float hlo = __int_as_float(hp << 16);
    float hhi = __int_as_float(hp & 0xFFFF0000u);
    float llo = vlo - hlo, lhi = vhi - hhi;
    asm("cvt.rn.bf16x2.f32 %0, %1, %2;" : "=r"(lp) : "f"(lhi), "f"(llo));
}

// fast 2^x for x <= ~1 (clamped at -126), err ~2e-6, FMA/ALU pipes only
__device__ __forceinline__ float fexp2(float x) {
    x = fmaxf(x, -126.0f);
    float fi = x + 12582912.0f;                      // round-to-nearest-int
    int   i  = __float_as_int(fi) - 0x4B400000;
    float f  = x - (fi - 12582912.0f);               // f in [-0.5, 0.5]
    float p  = 0.00133336f;
    p = fmaf(p, f, 0.00961813f);
    p = fmaf(p, f, 0.05550411f);
    p = fmaf(p, f, 0.24022651f);
    p = fmaf(p, f, 0.69314718f);
    p = fmaf(p, f, 1.0f);
    return p * __int_as_float((i + 127) << 23);
}

// u32-pair permutation within groups of 8: (tig, tig+4) -> (2tig, 2tig+1)
__device__ __forceinline__ int perm8(int o) { return (o < 4) ? 2 * o : 2 * (o - 4) + 1; }

// ---------------------------------------------------------------------------
// Split kernels (unchanged from R6)
// ---------------------------------------------------------------------------
__global__ void __launch_bounds__(256) split_kernel(
    const float4* __restrict__ src, __nv_bfloat162* __restrict__ hi,
    __nv_bfloat162* __restrict__ lo, int n4)
{
    int i = blockIdx.x * 256 + threadIdx.x;
    if (i >= n4) return;
    float4 v = src[i];
    __nv_bfloat16 h0 = __float2bfloat16(v.x), h1 = __float2bfloat16(v.y);
    __nv_bfloat16 h2 = __float2bfloat16(v.z), h3 = __float2bfloat16(v.w);
    __nv_bfloat16 l0 = __float2bfloat16(v.x - __bfloat162float(h0));
    __nv_bfloat16 l1 = __float2bfloat16(v.y - __bfloat162float(h1));
    __nv_bfloat16 l2 = __float2bfloat16(v.z - __bfloat162float(h2));
    __nv_bfloat16 l3 = __float2bfloat16(v.w - __bfloat162float(h3));
    __nv_bfloat162 a; a.x = h0; a.y = h1;
    __nv_bfloat162 b; b.x = h2; b.y = h3;
    __nv_bfloat162 c; c.x = l0; c.y = l1;
    __nv_bfloat162 d; d.x = l2; d.y = l3;
    hi[2 * i] = a;  hi[2 * i + 1] = b;
    lo[2 * i] = c;  lo[2 * i + 1] = d;
}

__global__ void __launch_bounds__(256) split_transpose_kernel(
    const float* __restrict__ src, __nv_bfloat16* __restrict__ hi,
    __nv_bfloat16* __restrict__ lo, int R, int C)
{
    __shared__ float t[32][33];
    int c0 = blockIdx.x * 32, r0 = blockIdx.y * 32;
    int tx = threadIdx.x, ty = threadIdx.y;
    #pragma unroll
    for (int i = 0; i < 4; i++) {
        int r = r0 + ty + i * 8;
        t[ty + i * 8][tx] = src[(size_t)r * C + c0 + tx];
    }
    __syncthreads();
    #pragma unroll
    for (int i = 0; i < 4; i++) {
        int n = c0 + ty + i * 8;
        float v = t[tx][ty + i * 8];
        __nv_bfloat16 h = __float2bfloat16(v);
        hi[(size_t)n * R + r0 + tx] = h;
        lo[(size_t)n * R + r0 + tx] = __float2bfloat16(v - __bfloat162float(h));
    }
}

// ---------------------------------------------------------------------------
// HMMA bf16-split GEMM (R6, + occupancy 2)
// ---------------------------------------------------------------------------
#define BM 128
#define BN 128
#define BK 32
#define ROW_U32 20
#define TILE_U32 (128 * ROW_U32)
#define STAGE_U32 (4 * TILE_U32)
#define GEMM_SMEM (2 * STAGE_U32 * 4)

__global__ void __launch_bounds__(256, 2)
gemm_mma_kernel(const __nv_bfloat16* __restrict__ Ah,
                const __nv_bfloat16* __restrict__ Al,
                const __nv_bfloat16* __restrict__ Bth,
                const __nv_bfloat16* __restrict__ Btl,
                const float* __restrict__ bias, float* __restrict__ C,
                int M, int N, int K)
{
    extern __shared__ uint32_t smem[];
    const int tid  = threadIdx.x;
    const int wid  = tid >> 5;
    const int lane = tid & 31;
    const int gid  = lane >> 2;
    const int tig  = lane & 3;
    const int wm   = (wid & 3) * 32;
    const int wn   = (wid >> 2) * 64;

    const int brow = blockIdx.y * BM;
    const int bcol = blockIdx.x * BN;

    const int prow = tid >> 2;
    const int pc4  = tid & 3;

    const __nv_bfloat16* srcs[4];
    srcs[0] = Ah  + (size_t)(brow + prow) * K + pc4 * 8;
    srcs[1] = Al  + (size_t)(brow + prow) * K + pc4 * 8;
    srcs[2] = Bth + (size_t)(bcol + prow) * K + pc4 * 8;
    srcs[3] = Btl + (size_t)(bcol + prow) * K + pc4 * 8;

    const uint32_t sb = smem_u32(smem);
    const uint32_t dst_base = sb + 4u * ((uint32_t)prow * ROW_U32 + pc4 * 4);

    const int NKB = K / BK;

    #pragma unroll
    for (int t = 0; t < 4; t++) {
        uint32_t d = dst_base + 4u * (uint32_t)(t * TILE_U32);
        CP_ASYNC16(d, srcs[t]);
        CP_ASYNC16(d + 4u * 64u * ROW_U32, srcs[t] + (size_t)64 * K);
    }
    CP_COMMIT();

    float acc[2][8][4];
    #pragma unroll
    for (int mt = 0; mt < 2; mt++)
        #pragma unroll
        for (int nt = 0; nt < 8; nt++)
            #pragma unroll
            for (int e = 0; e < 4; e++) acc[mt][nt][e] = 0.0f;

    for (int kb = 0; kb < NKB; kb++) {
        if (kb + 1 < NKB) {
            const int k0 = (kb + 1) * BK;
            const uint32_t stg = 4u * (uint32_t)(((kb + 1) & 1) * STAGE_U32);
            #pragma unroll
            for (int t = 0; t < 4; t++) {
                uint32_t d = dst_base + stg + 4u * (uint32_t)(t * TILE_U32);
                CP_ASYNC16(d, srcs[t] + k0);
                CP_ASYNC16(d + 4u * 64u * ROW_U32, srcs[t] + k0 + (size_t)64 * K);
            }
            CP_COMMIT();
            CP_WAIT(1);
        } else {
            CP_WAIT(0);
        }
        __syncthreads();

        const uint32_t* st   = smem + (kb & 1) * STAGE_U32;
        const uint32_t* Ah_s = st;
        const uint32_t* Al_s = st + TILE_U32;
        const uint32_t* Bh_s = st + 2 * TILE_U32;
        const uint32_t* Bl_s = st + 3 * TILE_U32;

        #pragma unroll
        for (int ks = 0; ks < 2; ks++) {
            const int k0u = ks * 8;
            uint32_t ah[2][4], al[2][4];
            #pragma unroll
            for (int mt = 0; mt < 2; mt++) {
                const int r = wm + mt * 16 + gid;
                ah[mt][0] = Ah_s[r * ROW_U32 + k0u + tig];
                ah[mt][1] = Ah_s[(r + 8) * ROW_U32 + k0u + tig];
                ah[mt][2] = Ah_s[r * ROW_U32 + k0u + 4 + tig];
                ah[mt][3] = Ah_s[(r + 8) * ROW_U32 + k0u + 4 + tig];
                al[mt][0] = Al_s[r * ROW_U32 + k0u + tig];
                al[mt][1] = Al_s[(r + 8) * ROW_U32 + k0u + tig];
                al[mt][2] = Al_s[r * ROW_U32 + k0u + 4 + tig];
                al[mt][3] = Al_s[(r + 8) * ROW_U32 + k0u + 4 + tig];
            }
            #pragma unroll
            for (int nt = 0; nt < 8; nt++) {
                const int n = wn + nt * 8 + gid;
                uint32_t bh[2], bl[2];
                bh[0] = Bh_s[n * ROW_U32 + k0u + tig];
                bh[1] = Bh_s[n * ROW_U32 + k0u + 4 + tig];
                bl[0] = Bl_s[n * ROW_U32 + k0u + tig];
                bl[1] = Bl_s[n * ROW_U32 + k0u + 4 + tig];
                #pragma unroll
                for (int mt = 0; mt < 2; mt++) {
                    mma_bf16(acc[mt][nt], ah[mt], bh);
                    mma_bf16(acc[mt][nt], ah[mt], bl);
                    mma_bf16(acc[mt][nt], al[mt], bh);
                }
            }
        }
        __syncthreads();
    }

    #pragma unroll
    for (int mt = 0; mt < 2; mt++) {
        const int gr = brow + wm + mt * 16 + gid;
        #pragma unroll
        for (int nt = 0; nt < 8; nt++) {
            const int gc = bcol + wn + nt * 8 + tig * 2;
            const float2 bb = *(const float2*)(bias + gc);
            float2 o0, o1;
            o0.x = acc[mt][nt][0] + bb.x;  o0.y = acc[mt][nt][1] + bb.y;
            o1.x = acc[mt][nt][2] + bb.x;  o1.y = acc[mt][nt][3] + bb.y;
            *(float2*)(C + (size_t)gr * N + gc)       = o0;
            *(float2*)(C + (size_t)(gr + 8) * N + gc) = o1;
        }
    }
}

// ---------------------------------------------------------------------------
// Prep kernels: g_qkv (fp32) -> flash bf16-split operand arrays
// ---------------------------------------------------------------------------
__global__ void __launch_bounds__(256) prep_qk_kernel()
{
    int t = blockIdx.x * 256 + threadIdx.x;     // B*H*S*32 threads
    int d2 = t & 31;
    int s  = (t >> 5) & (S_ - 1);
    int bh = t >> 16;                           // 0..31
    int h = bh & (H_ - 1), b = bh >> 4;
    size_t row = ((size_t)(b * S_ + s)) * NQKV_ + h * HD_ + 2 * d2;
    float2 q = *(const float2*)(g_qkv + row);
    float2 k = *(const float2*)(g_qkv + row + D_);
    int outc = (d2 & ~7) | perm8(d2 & 7);
    size_t oidx = ((size_t)bh * S_ + s) * 32 + outc;
    const float C = 0.18033688f;                // 0.125 * log2(e)
    q.x *= C; q.y *= C;
    uint32_t qh, ql, kh, kl;
    psplit(q.x, q.y, qh, ql);
    psplit(k.x, k.y, kh, kl);
    ((uint32_t*)g_fqh)[oidx] = qh;  ((uint32_t*)g_fql)[oidx] = ql;
    ((uint32_t*)g_fkh)[oidx] = kh;  ((uint32_t*)g_fkl)[oidx] = kl;
}

__global__ void __launch_bounds__(256) prep_v_kernel()
{
    __shared__ float tile[64][65];
    int s0 = blockIdx.x * 64, h = blockIdx.y, b = blockIdx.z;
    int tid = threadIdx.x;
    for (int i = tid; i < 64 * 64; i += 256) {
        int r = i >> 6, d = i & 63;
        tile[r][d] = g_qkv[((size_t)(b * S_ + s0 + r)) * NQKV_ + 2 * D_ + h * HD_ + d];
    }
    __syncthreads();
    int bh = b * H_ + h;
    for (int i = tid; i < 64 * 32; i += 256) {
        int d = i >> 5, s2 = i & 31;
        float v0 = tile[2 * s2][d], v1 = tile[2 * s2 + 1][d];
        uint32_t vh, vl;
        psplit(v0, v1, vh, vl);
        int sp = (s0 >> 1) + s2;
        int outc = (sp & ~7) | perm8(sp & 7);
        size_t oidx = ((size_t)bh * HD_ + d) * (S_ / 2) + outc;
        ((uint32_t*)g_fvh)[oidx] = vh;
        ((uint32_t*)g_fvl)[oidx] = vl;
    }
}

// ---------------------------------------------------------------------------
// Flash attention on HMMA. CTA = (128 q-rows, head, batch), 8 warps.
// Warp w owns q rows [16w,16w+16). Causal, streaming softmax in log2 domain.
// smem (bytes): Q h/l 2*20480 | stage{0,1}: K h/l 2*20480 + Vt h/l 2*18432
// ---------------------------------------------------------------------------
#define FLASH_SMEM 196608

__device__ __forceinline__ void flash_issue_tile(uint32_t sb, int tid, int bh,
                                                 int kt, int st)
{
    const char* kh = ((const char*)g_fkh) + ((size_t)(bh * S_ + kt * 128)) * 128;
    const char* kl = ((const char*)g_fkl) + ((size_t)(bh * S_ + kt * 128)) * 128;
    const char* vh = ((const char*)g_fvh) + (size_t)bh * HD_ * (S_ * 2) + kt * 256;
    const char* vl = ((const char*)g_fvl) + (size_t)bh * HD_ * (S_ * 2) + kt * 256;
    const uint32_t stg = sb + 40960u + (uint32_t)st * 77824u;
    #pragma unroll
    for (int p = 0; p < 4; p++) {
        int c = p * 256 + tid;
        int rowk = c >> 3, chk = c & 7;
        CP_ASYNC16(stg + rowk * 160 + chk * 16, kh + rowk * 128 + chk * 16);
        CP_ASYNC16(stg + 20480 + rowk * 160 + chk * 16, kl + rowk * 128 + chk * 16);
        int rowv = c >> 4, chv = c & 15;
        CP_ASYNC16(stg + 40960 + rowv * 288 + chv * 16,
                   vh + (size_t)rowv * (S_ * 2) + chv * 16);
        CP_ASYNC16(stg + 59392 + rowv * 288 + chv * 16,
                   vl + (size_t)rowv * (S_ * 2) + chv * 16);
    }
}

__global__ void __launch_bounds__(256, 1) flash_mma_kernel()
{
    extern __shared__ uint32_t fsm[];
    const uint32_t sb = smem_u32(fsm);
    const int tid = threadIdx.x, wid = tid >> 5, lane = tid & 31;
    const int gid = lane >> 2, tig = lane & 3;
    const int qt = blockIdx.x, h = blockIdx.y, b = blockIdx.z;
    const int bh = b * H_ + h;

    // Prologue: Q tile + K/V tile 0
    {
        const char* qsh = ((const char*)g_fqh) + ((size_t)(bh * S_ + qt * 128)) * 128;
        const char* qsl = ((const char*)g_fql) + ((size_t)(bh * S_ + qt * 128)) * 128;
        #pragma unroll
        for (int p = 0; p < 4; p++) {
            int c = p * 256 + tid;
            int row = c >> 3, ch = c & 7;
            CP_ASYNC16(sb + row * 160 + ch * 16, qsh + row * 128 + ch * 16);
            CP_ASYNC16(sb + 20480 + row * 160 + ch * 16, qsl + row * 128 + ch * 16);
        }
    }
    flash_issue_tile(sb, tid, bh, 0, 0);
    CP_COMMIT();

    float o[8][4];
    #pragma unroll
    for (int fo = 0; fo < 8; fo++)
        #pragma unroll
        for (int e = 0; e < 4; e++) o[fo][e] = 0.0f;
    float m0 = -INFINITY, m1 = -INFINITY, l0 = 0.0f, l1 = 0.0f;
    uint32_t qfh[4][4], qfl[4][4];

    for (int kt = 0; kt <= qt; kt++) {
        const int st = kt & 1;
        if (kt < qt) { flash_issue_tile(sb, tid, bh, kt + 1, st ^ 1); CP_COMMIT(); CP_WAIT(1); }
        else         { CP_WAIT(0); }
        __syncthreads();

        if (kt == 0) {   // load Q fragments once (resident in regs)
            const int r = wid * 16 + gid;
            #pragma unroll
            for (int kk = 0; kk < 4; kk++) {
                uint2 h0 = *(const uint2*)(fsm + r * 40 + 8 * kk + 2 * tig);
                uint2 h1 = *(const uint2*)(fsm + (r + 8) * 40 + 8 * kk + 2 * tig);
                qfh[kk][0] = h0.x; qfh[kk][1] = h1.x; qfh[kk][2] = h0.y; qfh[kk][3] = h1.y;
                uint2 l0v = *(const uint2*)(fsm + 5120 + r * 40 + 8 * kk + 2 * tig);
                uint2 l1v = *(const uint2*)(fsm + 5120 + (r + 8) * 40 + 8 * kk + 2 * tig);
                qfl[kk][0] = l0v.x; qfl[kk][1] = l1v.x; qfl[kk][2] = l0v.y; qfl[kk][3] = l1v.y;
            }
        }

        const uint32_t* Ks_h = fsm + 10240 + st * 19456;
        const uint32_t* Ks_l = Ks_h + 5120;
        const bool diag = (kt == qt);

        // S = Q K^T (3-MMA split), 16 n8 fragments over 128 keys
        float s[16][4];
        #pragma unroll
        for (int f = 0; f < 16; f++) {
            if (diag && (8 * f > 16 * wid + 15)) {
                s[f][0] = s[f][1] = s[f][2] = s[f][3] = -1e30f;
                continue;
            }
            float c4[4] = {0.0f, 0.0f, 0.0f, 0.0f};
            #pragma unroll
            for (int kk = 0; kk < 4; kk++) {
                uint2 bhv = *(const uint2*)(Ks_h + (8 * f + gid) * 40 + 8 * kk + 2 * tig);
                uint2 blv = *(const uint2*)(Ks_l + (8 * f + gid) * 40 + 8 * kk + 2 * tig);
                uint32_t bhf[2] = {bhv.x, bhv.y};
                uint32_t blf[2] = {blv.x, blv.y};
                mma_bf16(c4, qfh[kk], bhf);
                mma_bf16(c4, qfh[kk], blf);
                mma_bf16(c4, qfl[kk], bhf);
            }
            if (diag) {   // mask within diagonal tile
                int key = 8 * f + 2 * tig;
                int q0 = 16 * wid + gid, q1 = q0 + 8;
                if (key     > q0) c4[0] = -1e30f;
                if (key + 1 > q0) c4[1] = -1e30f;
                if (key     > q1) c4[2] = -1e30f;
                if (key + 1 > q1) c4[3] = -1e30f;
            }
            s[f][0] = c4[0]; s[f][1] = c4[1]; s[f][2] = c4[2]; s[f][3] = c4[3];
        }

        // streaming softmax (log2 domain; quad owns full rows)
        float rm0 = -1e30f, rm1 = -1e30f;
        #pragma unroll
        for (int f = 0; f < 16; f++) {
            rm0 = fmaxf(rm0, fmaxf(s[f][0], s[f][1]));
            rm1 = fmaxf(rm1, fmaxf(s[f][2], s[f][3]));
        }
        rm0 = fmaxf(rm0, __shfl_xor_sync(0xffffffffu, rm0, 1));
        rm0 = fmaxf(rm0, __shfl_xor_sync(0xffffffffu, rm0, 2));
        rm1 = fmaxf(rm1, __shfl_xor_sync(0xffffffffu, rm1, 1));
        rm1 = fmaxf(rm1, __shfl_xor_sync(0xffffffffu, rm1, 2));
        float mn0 = fmaxf(m0, rm0), mn1 = fmaxf(m1, rm1);
        float corr0 = fexp2(m0 - mn0), corr1 = fexp2(m1 - mn1);
        float rs0 = 0.0f, rs1 = 0.0f;
        #pragma unroll
        for (int f = 0; f < 16; f++) {
            s[f][0] = fexp2(s[f][0] - mn0);
            s[f][1] = fexp2(s[f][1] - mn0);
            s[f][2] = fexp2(s[f][2] - mn1);
            s[f][3] = fexp2(s[f][3] - mn1);
            rs0 += s[f][0] + s[f][1];
            rs1 += s[f][2] + s[f][3];
        }
        rs0 += __shfl_xor_sync(0xffffffffu, rs0, 1);
        rs0 += __shfl_xor_sync(0xffffffffu, rs0, 2);
        rs1 += __shfl_xor_sync(0xffffffffu, rs1, 1);
        rs1 += __shfl_xor_sync(0xffffffffu, rs1, 2);
        l0 = l0 * corr0 + rs0;  m0 = mn0;
        l1 = l1 * corr1 + rs1;  m1 = mn1;
        #pragma unroll
        for (int fo = 0; fo < 8; fo++) {
            o[fo][0] *= corr0;  o[fo][1] *= corr0;
            o[fo][2] *= corr1;  o[fo][3] *= corr1;
        }

        // convert P -> bf16 hi/lo A-fragments (register-resident)
        uint32_t ph[8][4], pl[8][4];
        #pragma unroll
        for (int j = 0; j < 8; j++) {
            if (diag && (j > wid)) continue;
            psplit(s[2 * j][0],     s[2 * j][1],     ph[j][0], pl[j][0]);
            psplit(s[2 * j][2],     s[2 * j][3],     ph[j][1], pl[j][1]);
            psplit(s[2 * j + 1][0], s[2 * j + 1][1], ph[j][2], pl[j][2]);
            psplit(s[2 * j + 1][2], s[2 * j + 1][3], ph[j][3], pl[j][3]);
        }

        // O += P V (3-MMA split), B = V^T [d][keys]
        const uint32_t* Vs_h = fsm + 10240 + st * 19456 + 10240;
        const uint32_t* Vs_l = Vs_h + 4608;
        #pragma unroll
        for (int j = 0; j < 8; j++) {
            if (diag && (j > wid)) continue;
            #pragma unroll
            for (int fo = 0; fo < 8; fo++) {
                uint2 vhv = *(const uint2*)(Vs_h + (8 * fo + gid) * 72 + 8 * j + 2 * tig);
                uint2 vlv = *(const uint2*)(Vs_l + (8 * fo + gid) * 72 + 8 * j + 2 * tig);
                uint32_t bhf[2] = {vhv.x, vhv.y};
                uint32_t blf[2] = {vlv.x, vlv.y};
                mma_bf16(o[fo], ph[j], bhf);
                mma_bf16(o[fo], pl[j], bhf);
                mma_bf16(o[fo], ph[j], blf);
            }
        }
        __syncthreads();
    }

    // normalize + write out: g_att[b, q, h*64 + d]
    float inv0 = 1.0f / l0, inv1 = 1.0f / l1;
    const int qr = qt * 128 + wid * 16 + gid;
    #pragma unroll
    for (int fo = 0; fo < 8; fo++) {
        int d = h * HD_ + 8 * fo + 2 * tig;
        float2 w0 = make_float2(o[fo][0] * inv0, o[fo][1] * inv0);
        float2 w1 = make_float2(o[fo][2] * inv1, o[fo][3] * inv1);
        *(float2*)(g_att + ((size_t)(b * S_ + qr)) * D_ + d)       = w0;
        *(float2*)(g_att + ((size_t)(b * S_ + qr + 8)) * D_ + d)   = w1;
    }
}

// ---------------------------------------------------------------------------
// kernel_launch
// ---------------------------------------------------------------------------
extern "C" void kernel_launch(void* const* d_in, const int* in_sizes, int n_in,
                              void* d_out, int out_size)
{
    const float* x     = (const float*)d_in[0];
    const float* qkv_w = (const float*)d_in[1];
    const float* qkv_b = (const float*)d_in[2];
    const float* out_w = (const float*)d_in[3];
    const float* out_b = (const float*)d_in[4];
    float* out = (float*)d_out;

    float *qkv_buf, *att_buf;
    __nv_bfloat16 *xh, *xl, *wh, *wl, *oh, *ol, *ah, *al;
    cudaGetSymbolAddress((void**)&qkv_buf, g_qkv);
    cudaGetSymbolAddress((void**)&att_buf, g_att);
    cudaGetSymbolAddress((void**)&xh, g_xh);
    cudaGetSymbolAddress((void**)&xl, g_xl);
    cudaGetSymbolAddress((void**)&wh, g_wh);
    cudaGetSymbolAddress((void**)&wl, g_wl);
    cudaGetSymbolAddress((void**)&oh, g_oh);
    cudaGetSymbolAddress((void**)&ol, g_ol);
    cudaGetSymbolAddress((void**)&ah, g_ah);
    cudaGetSymbolAddress((void**)&al, g_al);

    cudaFuncSetAttribute(gemm_mma_kernel,
                         cudaFuncAttributeMaxDynamicSharedMemorySize, GEMM_SMEM);
    cudaFuncSetAttribute(flash_mma_kernel,
                         cudaFuncAttributeMaxDynamicSharedMemorySize, FLASH_SMEM);

    // Split inputs
    {
        int n4 = MS_ * D_ / 4;
        split_kernel<<<(n4 + 255) / 256, 256>>>(
            (const float4*)x, (__nv_bfloat162*)xh, (__nv_bfloat162*)xl, n4);
    }
    split_transpose_kernel<<<dim3(NQKV_ / 32, D_ / 32), dim3(32, 8)>>>(
        qkv_w, wh, wl, D_, NQKV_);
    split_transpose_kernel<<<dim3(D_ / 32, D_ / 32), dim3(32, 8)>>>(
        out_w, oh, ol, D_, D_);

    // 1) QKV projection
    gemm_mma_kernel<<<dim3(NQKV_ / BN, MS_ / BM), 256, GEMM_SMEM>>>(
        xh, xl, wh, wl, qkv_b, qkv_buf, MS_, NQKV_, D_);

    // 2) prep flash operands, then flash attention on HMMA
    prep_qk_kernel<<<(B_ * H_ * S_ * 32) / 256, 256>>>();
    prep_v_kernel<<<dim3(S_ / 64, H_, B_), 256>>>();
    flash_mma_kernel<<<dim3(S_ / 128, H_, B_), 256, FLASH_SMEM>>>();

    // 3) output projection
    {
        int n4 = MS_ * D_ / 4;
        split_kernel<<<(n4 + 255) / 256, 256>>>(
            (const float4*)att_buf, (__nv_bfloat162*)ah, (__nv_bfloat162*)al, n4);
    }
    gemm_mma_kernel<<<dim3(D_ / BN, MS_ / BM), 256, GEMM_SMEM>>>(
        ah, al, oh, ol, out_b, out, MS_, D_, D_);
}

// round 12
// speedup vs baseline: 2.5826x; 1.0404x over previous
#include <cuda_runtime.h>
#include <cuda_bf16.h>
#include <math.h>
#include <stdint.h>

// Problem constants
#define B_  2
#define S_  2048
#define D_  1024
#define H_  16
#define HD_ 64
#define MS_ (B_ * S_)        // 4096 rows
#define NQKV_ (3 * D_)       // 3072

// ---------------------------------------------------------------------------
// Device-global scratch
// ---------------------------------------------------------------------------
__device__ float g_qkv[(size_t)MS_ * NQKV_];   // QKV projection output (fp32)

// bf16 splits, ALL in perm8 u32-pair layout (groups of 8 u32 permuted)
__device__ __nv_bfloat16 g_xh[(size_t)MS_ * D_],  g_xl[(size_t)MS_ * D_];
__device__ __nv_bfloat16 g_wh[(size_t)NQKV_ * D_], g_wl[(size_t)NQKV_ * D_]; // qkv_w^T
__device__ __nv_bfloat16 g_oh[(size_t)D_ * D_],   g_ol[(size_t)D_ * D_];     // out_w^T
__device__ __nv_bfloat16 g_ah[(size_t)MS_ * D_],  g_al[(size_t)MS_ * D_];    // att split

// flash operands: q/k: [b,h,s,d] (32 u32/row), v: [b,h,d,s-pairs] (1024 u32/row)
#define FQK_ELEMS ((size_t)B_ * H_ * S_ * HD_)
__device__ __nv_bfloat16 g_fqh[FQK_ELEMS], g_fql[FQK_ELEMS];
__device__ __nv_bfloat16 g_fkh[FQK_ELEMS], g_fkl[FQK_ELEMS];
__device__ __nv_bfloat16 g_fvh[FQK_ELEMS], g_fvl[FQK_ELEMS];

// ---------------------------------------------------------------------------
// Base-ISA helpers (no tcgen05/TMA: harness compiles for compute_103 base)
// ---------------------------------------------------------------------------
#define CP_ASYNC16(dst_u32, src_ptr) \
    asm volatile("cp.async.cg.shared.global [%0], [%1], 16;" \
                 :: "r"(dst_u32), "l"(src_ptr) : "memory")
#define CP_COMMIT() asm volatile("cp.async.commit_group;" ::: "memory")
#define CP_WAIT(n)  asm volatile("cp.async.wait_group %0;" :: "n"(n) : "memory")

__device__ __forceinline__ uint32_t smem_u32(const void* p) {
    uint32_t a;
    asm("{ .reg .u64 t; cvta.to.shared.u64 t, %1; cvt.u32.u64 %0, t; }"
        : "=r"(a) : "l"(p));
    return a;
}

__device__ __forceinline__ void mma_bf16(float* c, const uint32_t* a,
                                         const uint32_t* b) {
    asm volatile(
        "mma.sync.aligned.m16n8k16.row.col.f32.bf16.bf16.f32 "
        "{%0,%1,%2,%3}, {%4,%5,%6,%7}, {%8,%9}, {%0,%1,%2,%3};"
        : "+f"(c[0]), "+f"(c[1]), "+f"(c[2]), "+f"(c[3])
        : "r"(a[0]), "r"(a[1]), "r"(a[2]), "r"(a[3]), "r"(b[0]), "r"(b[1]));
}

__device__ __forceinline__ void psplit(float vlo, float vhi,
                                       uint32_t& hp, uint32_t& lp) {
    asm("cvt.rn.bf16x2.f32 %0, %1, %2;" : "=r"(hp) : "f"(vhi), "f"(vlo));
    float hlo = __int_as_float(hp << 16);
    float hhi = __int_as_float(hp & 0xFFFF0000u);
    float llo = vlo - hlo, lhi = vhi - hhi;
    asm("cvt.rn.bf16x2.f32 %0, %1, %2;" : "=r"(lp) : "f"(lhi), "f"(llo));
}

// fast 2^x, FMA/ALU pipes only
__device__ __forceinline__ float fexp2(float x) {
    x = fmaxf(x, -126.0f);
    float fi = x + 12582912.0f;
    int   i  = __float_as_int(fi) - 0x4B400000;
    float f  = x - (fi - 12582912.0f);
    float p  = 0.00133336f;
    p = fmaf(p, f, 0.00961813f);
    p = fmaf(p, f, 0.05550411f);
    p = fmaf(p, f, 0.24022651f);
    p = fmaf(p, f, 0.69314718f);
    p = fmaf(p, f, 1.0f);
    return p * __int_as_float((i + 127) << 23);
}

__device__ __forceinline__ int perm8(int o) { return (o < 4) ? 2 * o : 2 * (o - 4) + 1; }

// ---------------------------------------------------------------------------
// Split kernels -> perm8 layout
// ---------------------------------------------------------------------------
__global__ void __launch_bounds__(256) split_kernel_p(
    const float4* __restrict__ src, uint32_t* __restrict__ hi,
    uint32_t* __restrict__ lo, int n4)
{
    int i = blockIdx.x * 256 + threadIdx.x;
    if (i >= n4) return;
    float4 v = src[i];
    uint32_t h0, l0, h1, l1;
    psplit(v.x, v.y, h0, l0);
    psplit(v.z, v.w, h1, l1);
    int u0 = 2 * i;
    int base = u0 & ~7;
    int d0 = base + perm8(u0 & 7);
    int d1 = base + perm8((u0 + 1) & 7);
    hi[d0] = h0;  hi[d1] = h1;
    lo[d0] = l0;  lo[d1] = l1;
}

// Split + transpose + perm8: src [R,C] fp32 -> hi/lo [C,R] bf16 permuted rows
__global__ void __launch_bounds__(256) split_transpose_p(
    const float* __restrict__ src, __nv_bfloat16* __restrict__ hi,
    __nv_bfloat16* __restrict__ lo, int R, int C)
{
    __shared__ float t[32][33];
    int c0 = blockIdx.x * 32, r0 = blockIdx.y * 32;
    int tx = threadIdx.x, ty = threadIdx.y;
    #pragma unroll
    for (int i = 0; i < 4; i++) {
        int r = r0 + ty + i * 8;
        t[ty + i * 8][tx] = src[(size_t)r * C + c0 + tx];
    }
    __syncthreads();
    #pragma unroll
    for (int i = 0; i < 4; i++) {
        int n = c0 + ty + i * 8;
        float v = t[tx][ty + i * 8];
        __nv_bfloat16 h = __float2bfloat16(v);
        int e = r0 + tx;
        int ep = (e & ~15) + perm8((e >> 1) & 7) * 2 + (e & 1);
        hi[(size_t)n * R + ep] = h;
        lo[(size_t)n * R + ep] = __float2bfloat16(v - __bfloat162float(h));
    }
}

// ---------------------------------------------------------------------------
// HMMA bf16-split GEMM v2: perm8 inputs, zero-pad swizzled smem, 3-stage,
// one barrier per K-block, lds.64 fragments. 2 CTAs/SM.
// smem: 3 stages x 32KB (4 tiles x 128 rows x 64B)
// ---------------------------------------------------------------------------
#define GEMM_SMEM (3 * 32768)

// fragment pair offset in u32 units (row stride 16 u32, chunk-rotation swizzle)
__device__ __forceinline__ int gfrag(int r, int ks, int tig) {
    return r * 16 + (((2 * ks + (tig >> 1) + (r & 2)) & 3) << 2) + ((tig & 1) << 1);
}

__global__ void __launch_bounds__(256, 2)
gemm_mma_kernel(const __nv_bfloat16* __restrict__ Ah,
                const __nv_bfloat16* __restrict__ Al,
                const __nv_bfloat16* __restrict__ Bth,
                const __nv_bfloat16* __restrict__ Btl,
                const float* __restrict__ bias, float* __restrict__ C,
                int M, int N, int K)
{
    extern __shared__ uint32_t fsm[];
    const uint32_t sb = smem_u32(fsm);
    const int tid  = threadIdx.x;
    const int wid  = tid >> 5;
    const int lane = tid & 31;
    const int gid  = lane >> 2;
    const int tig  = lane & 3;
    const int wm   = (wid & 3) * 32;
    const int wn   = (wid >> 2) * 64;

    const int brow = blockIdx.y * 128;
    const int bcol = blockIdx.x * 128;
    const size_t rowb = (size_t)K * 2;    // bytes per row

    const char* base0 = (const char*)(Ah  + (size_t)brow * K);
    const char* base1 = (const char*)(Al  + (size_t)brow * K);
    const char* base2 = (const char*)(Bth + (size_t)bcol * K);
    const char* base3 = (const char*)(Btl + (size_t)bcol * K);

    const int NKB = K >> 5;

    // issue one stage (kb) into slot s
    auto issue = [&](int s, int kb) {
        const uint32_t stg = sb + (uint32_t)s * 32768u;
        #pragma unroll
        for (int p = 0; p < 8; p++) {
            int rem = (p & 1) * 256 + tid;
            int grow = rem >> 2, gch = rem & 3;
            uint32_t dst = stg + (uint32_t)(p >> 1) * 8192u + grow * 64 +
                           (((gch + (grow & 2)) & 3) << 4);
            const char* bptr = (p >> 1) == 0 ? base0 : (p >> 1) == 1 ? base1
                             : (p >> 1) == 2 ? base2 : base3;
            CP_ASYNC16(dst, bptr + (size_t)grow * rowb + kb * 64 + gch * 16);
        }
    };

    issue(0, 0); CP_COMMIT();
    issue(1, 1); CP_COMMIT();

    float acc[2][8][4];
    #pragma unroll
    for (int mt = 0; mt < 2; mt++)
        #pragma unroll
        for (int nt = 0; nt < 8; nt++)
            #pragma unroll
            for (int e = 0; e < 4; e++) acc[mt][nt][e] = 0.0f;

    for (int kb = 0; kb < NKB; kb++) {
        CP_WAIT(1);
        __syncthreads();
        const uint32_t* st   = fsm + (kb % 3) * 8192;
        const uint32_t* Ah_s = st;
        const uint32_t* Al_s = st + 2048;
        const uint32_t* Bh_s = st + 4096;
        const uint32_t* Bl_s = st + 6144;

        #pragma unroll
        for (int ks = 0; ks < 2; ks++) {
            uint32_t ah[2][4], al[2][4];
            #pragma unroll
            for (int mt = 0; mt < 2; mt++) {
                const int r = wm + mt * 16 + gid;
                uint2 h0 = *(const uint2*)(Ah_s + gfrag(r,     ks, tig));
                uint2 h1 = *(const uint2*)(Ah_s + gfrag(r + 8, ks, tig));
                uint2 l0 = *(const uint2*)(Al_s + gfrag(r,     ks, tig));
                uint2 l1 = *(const uint2*)(Al_s + gfrag(r + 8, ks, tig));
                ah[mt][0] = h0.x; ah[mt][1] = h1.x; ah[mt][2] = h0.y; ah[mt][3] = h1.y;
                al[mt][0] = l0.x; al[mt][1] = l1.x; al[mt][2] = l0.y; al[mt][3] = l1.y;
            }
            #pragma unroll
            for (int nt = 0; nt < 8; nt++) {
                const int n = wn + nt * 8 + gid;
                uint2 bh2 = *(const uint2*)(Bh_s + gfrag(n, ks, tig));
                uint2 bl2 = *(const uint2*)(Bl_s + gfrag(n, ks, tig));
                uint32_t bh[2] = {bh2.x, bh2.y};
                uint32_t bl[2] = {bl2.x, bl2.y};
                #pragma unroll
                for (int mt = 0; mt < 2; mt++) {
                    mma_bf16(acc[mt][nt], ah[mt], bh);
                    mma_bf16(acc[mt][nt], ah[mt], bl);
                    mma_bf16(acc[mt][nt], al[mt], bh);
                }
            }
        }
        if (kb + 2 < NKB) issue((kb + 2) % 3, kb + 2);
        CP_COMMIT();
    }

    #pragma unroll
    for (int mt = 0; mt < 2; mt++) {
        const int gr = brow + wm + mt * 16 + gid;
        #pragma unroll
        for (int nt = 0; nt < 8; nt++) {
            const int gc = bcol + wn + nt * 8 + tig * 2;
            const float2 bb = *(const float2*)(bias + gc);
            float2 o0, o1;
            o0.x = acc[mt][nt][0] + bb.x;  o0.y = acc[mt][nt][1] + bb.y;
            o1.x = acc[mt][nt][2] + bb.x;  o1.y = acc[mt][nt][3] + bb.y;
            *(float2*)(C + (size_t)gr * N + gc)       = o0;
            *(float2*)(C + (size_t)(gr + 8) * N + gc) = o1;
        }
    }
}

// ---------------------------------------------------------------------------
// Prep kernels: g_qkv (fp32) -> flash bf16-split operand arrays (perm8)
// ---------------------------------------------------------------------------
__global__ void __launch_bounds__(256) prep_qk_kernel()
{
    int t = blockIdx.x * 256 + threadIdx.x;
    int d2 = t & 31;
    int s  = (t >> 5) & (S_ - 1);
    int bh = t >> 16;
    int h = bh & (H_ - 1), b = bh >> 4;
    size_t row = ((size_t)(b * S_ + s)) * NQKV_ + h * HD_ + 2 * d2;
    float2 q = *(const float2*)(g_qkv + row);
    float2 k = *(const float2*)(g_qkv + row + D_);
    int outc = (d2 & ~7) | perm8(d2 & 7);
    size_t oidx = ((size_t)bh * S_ + s) * 32 + outc;
    const float Cc = 0.18033688f;                // 0.125 * log2(e)
    q.x *= Cc; q.y *= Cc;
    uint32_t qh, ql, kh, kl;
    psplit(q.x, q.y, qh, ql);
    psplit(k.x, k.y, kh, kl);
    ((uint32_t*)g_fqh)[oidx] = qh;  ((uint32_t*)g_fql)[oidx] = ql;
    ((uint32_t*)g_fkh)[oidx] = kh;  ((uint32_t*)g_fkl)[oidx] = kl;
}

__global__ void __launch_bounds__(256) prep_v_kernel()
{
    __shared__ float tile[64][65];
    int s0 = blockIdx.x * 64, h = blockIdx.y, b = blockIdx.z;
    int tid = threadIdx.x;
    for (int i = tid; i < 64 * 64; i += 256) {
        int r = i >> 6, d = i & 63;
        tile[r][d] = g_qkv[((size_t)(b * S_ + s0 + r)) * NQKV_ + 2 * D_ + h * HD_ + d];
    }
    __syncthreads();
    int bh = b * H_ + h;
    for (int i = tid; i < 64 * 32; i += 256) {
        int d = i >> 5, s2 = i & 31;
        float v0 = tile[2 * s2][d], v1 = tile[2 * s2 + 1][d];
        uint32_t vh, vl;
        psplit(v0, v1, vh, vl);
        int sp = (s0 >> 1) + s2;
        int outc = (sp & ~7) | perm8(sp & 7);
        size_t oidx = ((size_t)bh * HD_ + d) * (S_ / 2) + outc;
        ((uint32_t*)g_fvh)[oidx] = vh;
        ((uint32_t*)g_fvl)[oidx] = vl;
    }
}

// ---------------------------------------------------------------------------
// Flash attention v2: 64-key stages, 2 stages x 32KB = 64KB -> 2 CTAs/SM.
// Q fragments via LDG. Epilogue writes perm8 bf16-split (GEMM2 A operand).
// ---------------------------------------------------------------------------
#define FLASH_SMEM (2 * 32768)

// fragment offset, 32-u32 rows, chunk-rotation swizzle (8 chunks)
__device__ __forceinline__ int ffrag(int r, int kk, int tig) {
    return r * 32 + (((2 * kk + (tig >> 1) + 2 * r) & 7) << 2) + ((tig & 1) << 1);
}

__device__ __forceinline__ void flash_issue(uint32_t sb, int tid, int bh,
                                            int kt, int st)
{
    const char* kh = (const char*)g_fkh + ((size_t)bh * S_ + kt * 64) * 128;
    const char* kl = (const char*)g_fkl + ((size_t)bh * S_ + kt * 64) * 128;
    const char* vh = (const char*)g_fvh + ((size_t)bh * HD_) * 4096 + (size_t)kt * 128;
    const char* vl = (const char*)g_fvl + ((size_t)bh * HD_) * 4096 + (size_t)kt * 128;
    const uint32_t stg = sb + (uint32_t)st * 32768u;
    #pragma unroll
    for (int p = 0; p < 8; p++) {
        int rem = (p & 1) * 256 + tid;
        int row = rem >> 3, ch = rem & 7;
        uint32_t dst = stg + (uint32_t)(p >> 1) * 8192u + row * 128 +
                       (((ch + 2 * row) & 7) << 4);
        const char* src;
        if ((p >> 1) == 0)      src = kh + (size_t)row * 128 + ch * 16;
        else if ((p >> 1) == 1) src = kl + (size_t)row * 128 + ch * 16;
        else if ((p >> 1) == 2) src = vh + (size_t)row * 4096 + ch * 16;
        else                    src = vl + (size_t)row * 4096 + ch * 16;
        CP_ASYNC16(dst, src);
    }
}

__global__ void __launch_bounds__(256, 2) flash_mma_kernel()
{
    extern __shared__ uint32_t fsm[];
    const uint32_t sb = smem_u32(fsm);
    const int tid = threadIdx.x, wid = tid >> 5, lane = tid & 31;
    const int gid = lane >> 2, tig = lane & 3;
    const int qt = gridDim.x - 1 - blockIdx.x;   // longest CTAs first
    const int h = blockIdx.y, b = blockIdx.z;
    const int bh = b * H_ + h;

    // Q fragments via LDG (one-time)
    uint32_t qfh[4][4], qfl[4][4];
    {
        const uint2* qhp = (const uint2*)g_fqh;
        const uint2* qlp = (const uint2*)g_fql;
        size_t rb = ((size_t)bh * S_ + (size_t)qt * 128 + wid * 16 + gid) * 16;
        #pragma unroll
        for (int kk = 0; kk < 4; kk++) {
            uint2 h0 = qhp[rb + kk * 4 + tig];
            uint2 h1 = qhp[rb + 128 + kk * 4 + tig];
            qfh[kk][0] = h0.x; qfh[kk][1] = h1.x; qfh[kk][2] = h0.y; qfh[kk][3] = h1.y;
            uint2 l0 = qlp[rb + kk * 4 + tig];
            uint2 l1 = qlp[rb + 128 + kk * 4 + tig];
            qfl[kk][0] = l0.x; qfl[kk][1] = l1.x; qfl[kk][2] = l0.y; qfl[kk][3] = l1.y;
        }
    }

    flash_issue(sb, tid, bh, 0, 0);
    CP_COMMIT();

    float o[8][4];
    #pragma unroll
    for (int fo = 0; fo < 8; fo++)
        #pragma unroll
        for (int e = 0; e < 4; e++) o[fo][e] = 0.0f;
    float m0 = -INFINITY, m1 = -INFINITY, l0 = 0.0f, l1 = 0.0f;

    const int q0 = qt * 128 + 16 * wid + gid;
    const int q1 = q0 + 8;
    const int qmax = qt * 128 + 16 * wid + 15;
    const int KT = 2 * qt + 2;

    for (int kt = 0; kt < KT; kt++) {
        const int st = kt & 1;
        if (kt + 1 < KT) { flash_issue(sb, tid, bh, kt + 1, st ^ 1); CP_COMMIT(); CP_WAIT(1); }
        else             { CP_WAIT(0); }
        __syncthreads();

        const uint32_t* KH = fsm + st * 8192;
        const uint32_t* KL = KH + 2048;
        const uint32_t* VH = KH + 4096;
        const uint32_t* VL = KH + 6144;
        const bool diag = ((kt >> 1) == qt);

        // S = Q K^T (3-MMA split), 8 n8 fragments over 64 keys
        float s[8][4];
        #pragma unroll
        for (int f = 0; f < 8; f++) {
            const int key0 = kt * 64 + 8 * f;
            if (diag && key0 > qmax) {
                s[f][0] = s[f][1] = s[f][2] = s[f][3] = -1e30f;
                continue;
            }
            float c4[4] = {0.0f, 0.0f, 0.0f, 0.0f};
            #pragma unroll
            for (int kk = 0; kk < 4; kk++) {
                uint2 bh2 = *(const uint2*)(KH + ffrag(8 * f + gid, kk, tig));
                uint2 bl2 = *(const uint2*)(KL + ffrag(8 * f + gid, kk, tig));
                uint32_t bhf[2] = {bh2.x, bh2.y};
                uint32_t blf[2] = {bl2.x, bl2.y};
                mma_bf16(c4, qfh[kk], bhf);
                mma_bf16(c4, qfh[kk], blf);
                mma_bf16(c4, qfl[kk], bhf);
            }
            if (diag) {
                int key = key0 + 2 * tig;
                if (key     > q0) c4[0] = -1e30f;
                if (key + 1 > q0) c4[1] = -1e30f;
                if (key     > q1) c4[2] = -1e30f;
                if (key + 1 > q1) c4[3] = -1e30f;
            }
            s[f][0] = c4[0]; s[f][1] = c4[1]; s[f][2] = c4[2]; s[f][3] = c4[3];
        }

        // streaming softmax (log2 domain)
        float rm0 = -1e30f, rm1 = -1e30f;
        #pragma unroll
        for (int f = 0; f < 8; f++) {
            rm0 = fmaxf(rm0, fmaxf(s[f][0], s[f][1]));
            rm1 = fmaxf(rm1, fmaxf(s[f][2], s[f][3]));
        }
        rm0 = fmaxf(rm0, __shfl_xor_sync(0xffffffffu, rm0, 1));
        rm0 = fmaxf(rm0, __shfl_xor_sync(0xffffffffu, rm0, 2));
        rm1 = fmaxf(rm1, __shfl_xor_sync(0xffffffffu, rm1, 1));
        rm1 = fmaxf(rm1, __shfl_xor_sync(0xffffffffu, rm1, 2));
        float mn0 = fmaxf(m0, rm0), mn1 = fmaxf(m1, rm1);
        float corr0 = fexp2(m0 - mn0), corr1 = fexp2(m1 - mn1);
        float rs0 = 0.0f, rs1 = 0.0f;
        #pragma unroll
        for (int f = 0; f < 8; f++) {
            s[f][0] = fexp2(s[f][0] - mn0);
            s[f][1] = fexp2(s[f][1] - mn0);
            s[f][2] = fexp2(s[f][2] - mn1);
            s[f][3] = fexp2(s[f][3] - mn1);
            rs0 += s[f][0] + s[f][1];
            rs1 += s[f][2] + s[f][3];
        }
        rs0 += __shfl_xor_sync(0xffffffffu, rs0, 1);
        rs0 += __shfl_xor_sync(0xffffffffu, rs0, 2);
        rs1 += __shfl_xor_sync(0xffffffffu, rs1, 1);
        rs1 += __shfl_xor_sync(0xffffffffu, rs1, 2);
        l0 = l0 * corr0 + rs0;  m0 = mn0;
        l1 = l1 * corr1 + rs1;  m1 = mn1;
        #pragma unroll
        for (int fo = 0; fo < 8; fo++) {
            o[fo][0] *= corr0;  o[fo][1] *= corr0;
            o[fo][2] *= corr1;  o[fo][3] *= corr1;
        }

        // P -> bf16 hi/lo A-fragments
        uint32_t ph[4][4], pl[4][4];
        #pragma unroll
        for (int j = 0; j < 4; j++) {
            if (diag && (kt * 64 + 16 * j > qmax)) continue;
            psplit(s[2 * j][0],     s[2 * j][1],     ph[j][0], pl[j][0]);
            psplit(s[2 * j][2],     s[2 * j][3],     ph[j][1], pl[j][1]);
            psplit(s[2 * j + 1][0], s[2 * j + 1][1], ph[j][2], pl[j][2]);
            psplit(s[2 * j + 1][2], s[2 * j + 1][3], ph[j][3], pl[j][3]);
        }

        // O += P V (3-MMA split)
        #pragma unroll
        for (int j = 0; j < 4; j++) {
            if (diag && (kt * 64 + 16 * j > qmax)) continue;
            #pragma unroll
            for (int fo = 0; fo < 8; fo++) {
                uint2 vh2 = *(const uint2*)(VH + ffrag(8 * fo + gid, j, tig));
                uint2 vl2 = *(const uint2*)(VL + ffrag(8 * fo + gid, j, tig));
                uint32_t bhf[2] = {vh2.x, vh2.y};
                uint32_t blf[2] = {vl2.x, vl2.y};
                mma_bf16(o[fo], ph[j], bhf);
                mma_bf16(o[fo], pl[j], bhf);
                mma_bf16(o[fo], ph[j], blf);
            }
        }
        __syncthreads();
    }

    // normalize + write bf16 hi/lo split directly (perm8 GEMM-A layout)
    float inv0 = 1.0f / l0, inv1 = 1.0f / l1;
    uint32_t* AH = (uint32_t*)g_ah;
    uint32_t* AL = (uint32_t*)g_al;
    const size_t row0 = ((size_t)(b * S_) + q0) * 512;   // 512 u32 per row
    const size_t row1 = ((size_t)(b * S_) + q1) * 512;
    #pragma unroll
    for (int fo = 0; fo < 8; fo++) {
        int ucol = 4 * fo + tig;
        int pos = h * 32 + (ucol & ~7) + perm8(ucol & 7);
        uint32_t hp, lp;
        psplit(o[fo][0] * inv0, o[fo][1] * inv0, hp, lp);
        AH[row0 + pos] = hp;  AL[row0 + pos] = lp;
        psplit(o[fo][2] * inv1, o[fo][3] * inv1, hp, lp);
        AH[row1 + pos] = hp;  AL[row1 + pos] = lp;
    }
}

// ---------------------------------------------------------------------------
// kernel_launch
// ---------------------------------------------------------------------------
extern "C" void kernel_launch(void* const* d_in, const int* in_sizes, int n_in,
                              void* d_out, int out_size)
{
    const float* x     = (const float*)d_in[0];
    const float* qkv_w = (const float*)d_in[1];
    const float* qkv_b = (const float*)d_in[2];
    const float* out_w = (const float*)d_in[3];
    const float* out_b = (const float*)d_in[4];
    float* out = (float*)d_out;

    float *qkv_buf;
    __nv_bfloat16 *xh, *xl, *wh, *wl, *oh, *ol, *ah, *al;
    cudaGetSymbolAddress((void**)&qkv_buf, g_qkv);
    cudaGetSymbolAddress((void**)&xh, g_xh);
    cudaGetSymbolAddress((void**)&xl, g_xl);
    cudaGetSymbolAddress((void**)&wh, g_wh);
    cudaGetSymbolAddress((void**)&wl, g_wl);
    cudaGetSymbolAddress((void**)&oh, g_oh);
    cudaGetSymbolAddress((void**)&ol, g_ol);
    cudaGetSymbolAddress((void**)&ah, g_ah);
    cudaGetSymbolAddress((void**)&al, g_al);

    cudaFuncSetAttribute(gemm_mma_kernel,
                         cudaFuncAttributeMaxDynamicSharedMemorySize, GEMM_SMEM);
    cudaFuncSetAttribute(flash_mma_kernel,
                         cudaFuncAttributeMaxDynamicSharedMemorySize, FLASH_SMEM);

    // Split inputs (perm8 layout)
    {
        int n4 = MS_ * D_ / 4;
        split_kernel_p<<<(n4 + 255) / 256, 256>>>(
            (const float4*)x, (uint32_t*)xh, (uint32_t*)xl, n4);
    }
    split_transpose_p<<<dim3(NQKV_ / 32, D_ / 32), dim3(32, 8)>>>(
        qkv_w, wh, wl, D_, NQKV_);
    split_transpose_p<<<dim3(D_ / 32, D_ / 32), dim3(32, 8)>>>(
        out_w, oh, ol, D_, D_);

    // 1) QKV projection
    gemm_mma_kernel<<<dim3(NQKV_ / 128, MS_ / 128), 256, GEMM_SMEM>>>(
        xh, xl, wh, wl, qkv_b, qkv_buf, MS_, NQKV_, D_);

    // 2) prep flash operands, then flash attention (writes g_ah/g_al)
    prep_qk_kernel<<<(B_ * H_ * S_ * 32) / 256, 256>>>();
    prep_v_kernel<<<dim3(S_ / 64, H_, B_), 256>>>();
    flash_mma_kernel<<<dim3(S_ / 128, H_, B_), 256, FLASH_SMEM>>>();

    // 3) output projection
    gemm_mma_kernel<<<dim3(D_ / 128, MS_ / 128), 256, GEMM_SMEM>>>(
        ah, al, oh, ol, out_b, out, MS_, D_, D_);
}